// round 1
// baseline (speedup 1.0000x reference)
#include <cuda_runtime.h>
#include <math.h>

#define EMB   2048
#define NH    16
#define HD    128
#define BATCH 4
#define SEQ   2048
#define MTOT  (BATCH*SEQ)   // 8192 rows

// Scratch (device globals -- allocation-free per harness rules)
__device__ float g_q[(size_t)MTOT * EMB];
__device__ float g_k[(size_t)MTOT * EMB];
__device__ float g_v[(size_t)MTOT * EMB];
__device__ float g_ctx[(size_t)MTOT * EMB];

// ---------------------------------------------------------------------------
// SGEMM (NT): C[m][n] = sum_k A[m*K+k] * B[n*K+k]
// 128x128 block tile, BK=16, 256 threads, 8x8 per-thread register tile.
// ---------------------------------------------------------------------------
__global__ __launch_bounds__(256) void sgemm_nt(const float* __restrict__ A,
                                                const float* __restrict__ B,
                                                float* __restrict__ C,
                                                int M, int N, int K)
{
    __shared__ float As[16][132];
    __shared__ float Bs[16][132];

    const int tid = threadIdx.x;
    const int m0 = blockIdx.y * 128;
    const int n0 = blockIdx.x * 128;
    const int tr = tid >> 4;   // 0..15
    const int tc = tid & 15;   // 0..15

    float acc[8][8];
#pragma unroll
    for (int i = 0; i < 8; i++)
#pragma unroll
        for (int j = 0; j < 8; j++) acc[i][j] = 0.f;

    for (int k0 = 0; k0 < K; k0 += 16) {
        // Load A and B tiles (128 rows x 16 cols each), transposed into smem.
#pragma unroll
        for (int l = 0; l < 2; l++) {
            int idx = tid + l * 256;       // 0..511
            int row = idx >> 2;            // 0..127
            int c4  = idx & 3;             // 0..3 (float4 within the 16-col slab)
            float4 va = *(const float4*)(A + (size_t)(m0 + row) * K + k0 + c4 * 4);
            As[c4 * 4 + 0][row] = va.x;
            As[c4 * 4 + 1][row] = va.y;
            As[c4 * 4 + 2][row] = va.z;
            As[c4 * 4 + 3][row] = va.w;
            float4 vb = *(const float4*)(B + (size_t)(n0 + row) * K + k0 + c4 * 4);
            Bs[c4 * 4 + 0][row] = vb.x;
            Bs[c4 * 4 + 1][row] = vb.y;
            Bs[c4 * 4 + 2][row] = vb.z;
            Bs[c4 * 4 + 3][row] = vb.w;
        }
        __syncthreads();

#pragma unroll
        for (int kk = 0; kk < 16; kk++) {
            float a[8], b[8];
            *(float4*)(a)     = *(const float4*)&As[kk][tr * 8];
            *(float4*)(a + 4) = *(const float4*)&As[kk][tr * 8 + 4];
            *(float4*)(b)     = *(const float4*)&Bs[kk][tc * 8];
            *(float4*)(b + 4) = *(const float4*)&Bs[kk][tc * 8 + 4];
#pragma unroll
            for (int i = 0; i < 8; i++)
#pragma unroll
                for (int j = 0; j < 8; j++)
                    acc[i][j] = fmaf(a[i], b[j], acc[i][j]);
        }
        __syncthreads();
    }

#pragma unroll
    for (int i = 0; i < 8; i++) {
        size_t off = (size_t)(m0 + tr * 8 + i) * N + n0 + tc * 8;
        float4 v0 = make_float4(acc[i][0], acc[i][1], acc[i][2], acc[i][3]);
        float4 v1 = make_float4(acc[i][4], acc[i][5], acc[i][6], acc[i][7]);
        *(float4*)(C + off)     = v0;
        *(float4*)(C + off + 4) = v1;
    }
}

// ---------------------------------------------------------------------------
// RoPE (interleaved pairs), applied in-place to q and k.
// Angle computed in double so our inv_freq matches the f32 reference to
// well under the rel-err budget.
// ---------------------------------------------------------------------------
__global__ void rope_kernel(float* __restrict__ q, float* __restrict__ k)
{
    int idx = blockIdx.x * blockDim.x + threadIdx.x;   // over MTOT*NH*64 pairs
    if (idx >= MTOT * NH * (HD / 2)) return;
    int i = idx & 63;            // pair index 0..63
    int h = (idx >> 6) & 15;     // head
    int m = idx >> 10;           // row 0..8191
    int s = m & (SEQ - 1);       // position within sequence

    double freq = pow(10000.0, -(double)i / 64.0);
    float ang = (float)((double)s * freq);
    float sn, cs;
    sincosf(ang, &sn, &cs);

    size_t base = (size_t)m * EMB + h * HD + 2 * i;
    float q1 = q[base], q2 = q[base + 1];
    q[base]     = q1 * cs - q2 * sn;
    q[base + 1] = q2 * cs + q1 * sn;
    float k1 = k[base], k2 = k[base + 1];
    k[base]     = k1 * cs - k2 * sn;
    k[base + 1] = k2 * cs + k1 * sn;
}

// ---------------------------------------------------------------------------
// Flash attention (fp32), causal. One block per (q-tile of 64 rows, b*h).
// 256 threads. Online softmax. Skips fully-masked k tiles (kt > qt).
// ---------------------------------------------------------------------------
#define BQ   64
#define BKV  64
#define QP   129   // Qs/Ks row pad (scalar access)
#define VP   132   // Vs row pad (float4 access -> multiple of 4)
#define SP   65    // Ss row pad

__global__ __launch_bounds__(256) void flash_kernel(const float* __restrict__ q,
                                                    const float* __restrict__ k,
                                                    const float* __restrict__ v,
                                                    float* __restrict__ ctx)
{
    extern __shared__ float sm[];
    float* Qs   = sm;                      // 64*129
    float* Ks   = Qs + BQ * QP;            // 64*129
    float* Vs   = Ks + BKV * QP;           // 64*132
    float* Ss   = Vs + BKV * VP;           // 64*65
    float* mrow = Ss + BQ * SP;            // 64
    float* lrow = mrow + BQ;               // 64
    float* srow = lrow + BQ;               // 64

    const int qt  = blockIdx.x;            // 0..31
    const int bh  = blockIdx.y;            // 0..63
    const int b   = bh >> 4;
    const int h   = bh & 15;
    const int tid = threadIdx.x;
    const float scale = 0.08838834764831845f;  // 1/sqrt(128)

    // Load Q tile (scaled): 64 rows x 128 cols
#pragma unroll
    for (int l = 0; l < 8; l++) {
        int idx = tid + l * 256;           // float4 index 0..2047
        int r  = idx >> 5;
        int c4 = idx & 31;
        float4 vq = *(const float4*)(q + (size_t)(b * SEQ + qt * BQ + r) * EMB + h * HD + c4 * 4);
        float* dst = &Qs[r * QP + c4 * 4];
        dst[0] = vq.x * scale; dst[1] = vq.y * scale;
        dst[2] = vq.z * scale; dst[3] = vq.w * scale;
    }
    if (tid < BQ) { mrow[tid] = -1e30f; lrow[tid] = 0.f; }

    float acc[4][8];
#pragma unroll
    for (int i = 0; i < 4; i++)
#pragma unroll
        for (int j = 0; j < 8; j++) acc[i][j] = 0.f;

    const int ty = tid >> 4;               // 0..15
    const int tx = tid & 15;               // 0..15
    const int ro = ty * 4;                 // PV / S-compute rows
    const int co = tx * 8;                 // PV cols

    for (int kt = 0; kt <= qt; kt++) {
        __syncthreads();   // previous PV done; Qs visible (first iter)
        // Load K, V tiles
#pragma unroll
        for (int l = 0; l < 8; l++) {
            int idx = tid + l * 256;
            int r  = idx >> 5;
            int c4 = idx & 31;
            size_t goff = (size_t)(b * SEQ + kt * BKV + r) * EMB + h * HD + c4 * 4;
            float4 vk = *(const float4*)(k + goff);
            float* dk = &Ks[r * QP + c4 * 4];
            dk[0] = vk.x; dk[1] = vk.y; dk[2] = vk.z; dk[3] = vk.w;
            float4 vv = *(const float4*)(v + goff);
            *(float4*)&Vs[r * VP + c4 * 4] = vv;
        }
        __syncthreads();

        // S = Q K^T  (4x4 per thread)
        float s_[4][4];
#pragma unroll
        for (int i = 0; i < 4; i++)
#pragma unroll
            for (int j = 0; j < 4; j++) s_[i][j] = 0.f;
#pragma unroll 4
        for (int d = 0; d < HD; d++) {
            float aq[4], ak[4];
#pragma unroll
            for (int i = 0; i < 4; i++) aq[i] = Qs[(ro + i) * QP + d];
#pragma unroll
            for (int j = 0; j < 4; j++) ak[j] = Ks[(tx * 4 + j) * QP + d];
#pragma unroll
            for (int i = 0; i < 4; i++)
#pragma unroll
                for (int j = 0; j < 4; j++)
                    s_[i][j] = fmaf(aq[i], ak[j], s_[i][j]);
        }
        // Mask + store
#pragma unroll
        for (int i = 0; i < 4; i++)
#pragma unroll
            for (int j = 0; j < 4; j++) {
                int r = ro + i, c = tx * 4 + j;
                float val = s_[i][j];
                if (kt == qt && c > r) val = -1e30f;
                Ss[r * SP + c] = val;
            }
        __syncthreads();

        // Online softmax: 4 threads per row (16 cols each)
        {
            int row = tid >> 2, seg = tid & 3;
            float pm = -1e30f;
            for (int c = seg * 16; c < seg * 16 + 16; c++)
                pm = fmaxf(pm, Ss[row * SP + c]);
            pm = fmaxf(pm, __shfl_xor_sync(0xffffffff, pm, 1));
            pm = fmaxf(pm, __shfl_xor_sync(0xffffffff, pm, 2));
            float mold = mrow[row];
            float mnew = fmaxf(mold, pm);
            float psum = 0.f;
            for (int c = seg * 16; c < seg * 16 + 16; c++) {
                float p = __expf(Ss[row * SP + c] - mnew);
                Ss[row * SP + c] = p;
                psum += p;
            }
            psum += __shfl_xor_sync(0xffffffff, psum, 1);
            psum += __shfl_xor_sync(0xffffffff, psum, 2);
            if (seg == 0) {
                float sc = __expf(mold - mnew);
                srow[row] = sc;
                lrow[row] = lrow[row] * sc + psum;
                mrow[row] = mnew;
            }
        }
        __syncthreads();

        // Rescale accumulators + PV (4 rows x 8 cols per thread)
        float sc[4];
#pragma unroll
        for (int i = 0; i < 4; i++) sc[i] = srow[ro + i];
#pragma unroll
        for (int i = 0; i < 4; i++)
#pragma unroll
            for (int j = 0; j < 8; j++) acc[i][j] *= sc[i];

#pragma unroll 4
        for (int kk = 0; kk < BKV; kk++) {
            float p[4];
#pragma unroll
            for (int i = 0; i < 4; i++) p[i] = Ss[(ro + i) * SP + kk];
            float vv[8];
            *(float4*)(vv)     = *(const float4*)&Vs[kk * VP + co];
            *(float4*)(vv + 4) = *(const float4*)&Vs[kk * VP + co + 4];
#pragma unroll
            for (int i = 0; i < 4; i++)
#pragma unroll
                for (int j = 0; j < 8; j++)
                    acc[i][j] = fmaf(p[i], vv[j], acc[i][j]);
        }
    }

    // Write ctx
#pragma unroll
    for (int i = 0; i < 4; i++) {
        float inv = 1.0f / lrow[ro + i];
        size_t m = (size_t)(b * SEQ + qt * BQ + ro + i);
        float4 o0 = make_float4(acc[i][0] * inv, acc[i][1] * inv, acc[i][2] * inv, acc[i][3] * inv);
        float4 o1 = make_float4(acc[i][4] * inv, acc[i][5] * inv, acc[i][6] * inv, acc[i][7] * inv);
        *(float4*)(ctx + m * EMB + h * HD + co)     = o0;
        *(float4*)(ctx + m * EMB + h * HD + co + 4) = o1;
    }
}

// ---------------------------------------------------------------------------
// Launch
// ---------------------------------------------------------------------------
extern "C" void kernel_launch(void* const* d_in, const int* in_sizes, int n_in,
                              void* d_out, int out_size)
{
    const float* x  = (const float*)d_in[0];
    const float* Wq = (const float*)d_in[1];
    const float* Wk = (const float*)d_in[2];
    const float* Wv = (const float*)d_in[3];
    const float* Wo = (const float*)d_in[4];
    float* out = (float*)d_out;

    float *pq, *pk, *pv, *pctx;
    cudaGetSymbolAddress((void**)&pq,   g_q);
    cudaGetSymbolAddress((void**)&pk,   g_k);
    cudaGetSymbolAddress((void**)&pv,   g_v);
    cudaGetSymbolAddress((void**)&pctx, g_ctx);

    dim3 gg(EMB / 128, MTOT / 128);   // (16, 64)
    sgemm_nt<<<gg, 256>>>(x, Wq, pq, MTOT, EMB, EMB);
    sgemm_nt<<<gg, 256>>>(x, Wk, pk, MTOT, EMB, EMB);
    sgemm_nt<<<gg, 256>>>(x, Wv, pv, MTOT, EMB, EMB);

    int npairs = MTOT * NH * (HD / 2);
    rope_kernel<<<(npairs + 255) / 256, 256>>>(pq, pk);

    size_t smem = (size_t)(BQ * QP + BKV * QP + BKV * VP + BQ * SP + 3 * BQ) * sizeof(float);
    static bool attr_set = false;
    cudaFuncSetAttribute(flash_kernel, cudaFuncAttributeMaxDynamicSharedMemorySize, (int)smem);
    (void)attr_set;
    dim3 gf(SEQ / BQ, BATCH * NH);    // (32, 64)
    flash_kernel<<<gf, 256, smem>>>(pq, pk, pv, pctx);

    sgemm_nt<<<gg, 256>>>(pctx, Wo, out, MTOT, EMB, EMB);
}

// round 8
// speedup vs baseline: 1.5009x; 1.5009x over previous
#include <cuda_runtime.h>
#include <cuda_bf16.h>
#include <math.h>
#include <stdint.h>

#define EMB   2048
#define NH    16
#define HD    128
#define BATCH 4
#define SEQ   2048
#define MTOT  (BATCH*SEQ)   // 8192 rows
#define GK    2048          // GEMM K (fixed)

// Scratch (device globals -- allocation-free per harness rules)
__device__ float g_q[(size_t)MTOT * EMB];
__device__ float g_k[(size_t)MTOT * EMB];
__device__ float g_v[(size_t)MTOT * EMB];
__device__ float g_ctx[(size_t)MTOT * EMB];

// ===========================================================================
// Small PTX helpers (all baseline sm_80+ -- compiles on plain sm_103 target)
// ===========================================================================
__device__ __forceinline__ uint32_t smem_u32(const void* p) {
    uint32_t a;
    asm("{ .reg .u64 t; cvta.to.shared.u64 t, %1; cvt.u32.u64 %0, t; }" : "=r"(a) : "l"(p));
    return a;
}
__device__ __forceinline__ void ldsm4(uint32_t* r, uint32_t addr) {
    asm volatile("ldmatrix.sync.aligned.m8n8.x4.shared.b16 {%0,%1,%2,%3}, [%4];"
        : "=r"(r[0]), "=r"(r[1]), "=r"(r[2]), "=r"(r[3]) : "r"(addr));
}
__device__ __forceinline__ void mma_bf16(float* d, const uint32_t* a, uint32_t b0, uint32_t b1) {
    asm volatile("mma.sync.aligned.m16n8k16.row.col.f32.bf16.bf16.f32 "
        "{%0,%1,%2,%3}, {%4,%5,%6,%7}, {%8,%9}, {%0,%1,%2,%3};"
        : "+f"(d[0]), "+f"(d[1]), "+f"(d[2]), "+f"(d[3])
        : "r"(a[0]), "r"(a[1]), "r"(a[2]), "r"(a[3]), "r"(b0), "r"(b1));
}

// ===========================================================================
// bf16-split HMMA GEMM (NT): C[m][n] = sum_k A[m*K+k] * B[n*K+k], fp32 in/out.
// CTA tile 128x128, BK=32, 256 threads = 8 warps (2m x 4n), warp tile 64x32.
// A,B split on the fly into bf16 hi/lo; D = Ah*Bh + Ah*Bl + Al*Bh (fp32 acc).
// AST = 40 bf16 elems = 80 bytes/row: 16B-aligned rows for ldmatrix
// (80 % 16 == 0) and conflict-free phases (stride 20 banks: 0,20,8,28,...).
// ===========================================================================
#define BM 128
#define BN 128
#define BKK 32
#define AST 40

__global__ __launch_bounds__(256, 1) void mma_gemm(const float* __restrict__ A,
                                                   const float* __restrict__ B,
                                                   float* __restrict__ C,
                                                   int M, int N)
{
    __shared__ __align__(16) __nv_bfloat16 Ah[BM * AST];
    __shared__ __align__(16) __nv_bfloat16 Al[BM * AST];
    __shared__ __align__(16) __nv_bfloat16 Bh[BN * AST];
    __shared__ __align__(16) __nv_bfloat16 Bl[BN * AST];

    const int tid  = threadIdx.x;
    const int lane = tid & 31;
    const int wid  = tid >> 5;
    const int m0 = blockIdx.y * BM;
    const int n0 = blockIdx.x * BN;
    const int wm = (wid & 1) * 64;    // warp m offset within CTA tile
    const int wn = (wid >> 1) * 32;   // warp n offset within CTA tile

    float acc[4][4][4];               // [mt][nt][reg]
#pragma unroll
    for (int i = 0; i < 4; i++)
#pragma unroll
        for (int j = 0; j < 4; j++)
#pragma unroll
            for (int r = 0; r < 4; r++) acc[i][j][r] = 0.f;

    // ldmatrix base addresses (bytes): row = (lane&15), col-half = (lane>>4)*8
    const uint32_t lrow = (lane & 15);
    const uint32_t lcol = (lane >> 4) * 8;   // bf16 elems
    const uint32_t a_base  = smem_u32(Ah) + ((wm + lrow) * AST + lcol) * 2;
    const uint32_t al_base = smem_u32(Al) + ((wm + lrow) * AST + lcol) * 2;
    const uint32_t b_base  = smem_u32(Bh) + ((wn + lrow) * AST + lcol) * 2;
    const uint32_t bl_base = smem_u32(Bl) + ((wn + lrow) * AST + lcol) * 2;

    const int ldrow = tid >> 3;       // 0..31, +32 per unroll step
    const int ldk   = tid & 7;        // float4 slot within 32-col slab

    for (int k0 = 0; k0 < GK; k0 += BKK) {
        // ---- load + split-convert: A and B tiles are 128 rows x 32 k fp32 ----
#pragma unroll
        for (int l = 0; l < 4; l++) {
            int row = ldrow + l * 32;
            uint32_t soff = (uint32_t)(row * AST + ldk * 4) * 2;   // bytes

            float4 va = *(const float4*)(A + (size_t)(m0 + row) * GK + k0 + ldk * 4);
            __nv_bfloat162 h0 = __floats2bfloat162_rn(va.x, va.y);
            __nv_bfloat162 h1 = __floats2bfloat162_rn(va.z, va.w);
            __nv_bfloat162 e0 = __floats2bfloat162_rn(va.x - __bfloat162float(h0.x),
                                                      va.y - __bfloat162float(h0.y));
            __nv_bfloat162 e1 = __floats2bfloat162_rn(va.z - __bfloat162float(h1.x),
                                                      va.w - __bfloat162float(h1.y));
            *(__nv_bfloat162*)((char*)Ah + soff)     = h0;
            *(__nv_bfloat162*)((char*)Ah + soff + 4) = h1;
            *(__nv_bfloat162*)((char*)Al + soff)     = e0;
            *(__nv_bfloat162*)((char*)Al + soff + 4) = e1;

            float4 vb = *(const float4*)(B + (size_t)(n0 + row) * GK + k0 + ldk * 4);
            __nv_bfloat162 g0 = __floats2bfloat162_rn(vb.x, vb.y);
            __nv_bfloat162 g1 = __floats2bfloat162_rn(vb.z, vb.w);
            __nv_bfloat162 f0 = __floats2bfloat162_rn(vb.x - __bfloat162float(g0.x),
                                                      vb.y - __bfloat162float(g0.y));
            __nv_bfloat162 f1 = __floats2bfloat162_rn(vb.z - __bfloat162float(g1.x),
                                                      vb.w - __bfloat162float(g1.y));
            *(__nv_bfloat162*)((char*)Bh + soff)     = g0;
            *(__nv_bfloat162*)((char*)Bh + soff + 4) = g1;
            *(__nv_bfloat162*)((char*)Bl + soff)     = f0;
            *(__nv_bfloat162*)((char*)Bl + soff + 4) = f1;
        }
        __syncthreads();

        // ---- MMA: two k16 steps ----
#pragma unroll
        for (int ks = 0; ks < 2; ks++) {
            const uint32_t kb = ks * 32;   // 16 bf16 = 32 bytes

            uint32_t afh[4][4], bfh[2][4];
#pragma unroll
            for (int mt = 0; mt < 4; mt++)
                ldsm4(afh[mt], a_base + mt * (16 * AST * 2) + kb);
#pragma unroll
            for (int nh = 0; nh < 2; nh++)
                ldsm4(bfh[nh], b_base + nh * (16 * AST * 2) + kb);

            // hi * hi
#pragma unroll
            for (int mt = 0; mt < 4; mt++)
#pragma unroll
                for (int nt = 0; nt < 4; nt++)
                    mma_bf16(acc[mt][nt], afh[mt], bfh[nt >> 1][nt & 1], bfh[nt >> 1][(nt & 1) + 2]);

            // hi * lo
            uint32_t bfl[2][4];
#pragma unroll
            for (int nh = 0; nh < 2; nh++)
                ldsm4(bfl[nh], bl_base + nh * (16 * AST * 2) + kb);
#pragma unroll
            for (int mt = 0; mt < 4; mt++)
#pragma unroll
                for (int nt = 0; nt < 4; nt++)
                    mma_bf16(acc[mt][nt], afh[mt], bfl[nt >> 1][nt & 1], bfl[nt >> 1][(nt & 1) + 2]);

            // lo * hi
            uint32_t afl[4][4];
#pragma unroll
            for (int mt = 0; mt < 4; mt++)
                ldsm4(afl[mt], al_base + mt * (16 * AST * 2) + kb);
#pragma unroll
            for (int mt = 0; mt < 4; mt++)
#pragma unroll
                for (int nt = 0; nt < 4; nt++)
                    mma_bf16(acc[mt][nt], afl[mt], bfh[nt >> 1][nt & 1], bfh[nt >> 1][(nt & 1) + 2]);
        }
        __syncthreads();
    }

    // ---- epilogue: direct float2 stores ----
    const int erow = lane >> 2;
    const int ecol = (lane & 3) * 2;
#pragma unroll
    for (int mt = 0; mt < 4; mt++) {
#pragma unroll
        for (int nt = 0; nt < 4; nt++) {
            int row = m0 + wm + mt * 16 + erow;
            int col = n0 + wn + nt * 8 + ecol;
            *(float2*)(C + (size_t)row * N + col) =
                make_float2(acc[mt][nt][0], acc[mt][nt][1]);
            *(float2*)(C + (size_t)(row + 8) * N + col) =
                make_float2(acc[mt][nt][2], acc[mt][nt][3]);
        }
    }
}

// ---------------------------------------------------------------------------
// RoPE (interleaved pairs), applied in-place to q and k.
// ---------------------------------------------------------------------------
__global__ void rope_kernel(float* __restrict__ q, float* __restrict__ k)
{
    int idx = blockIdx.x * blockDim.x + threadIdx.x;
    if (idx >= MTOT * NH * (HD / 2)) return;
    int i = idx & 63;
    int h = (idx >> 6) & 15;
    int m = idx >> 10;
    int s = m & (SEQ - 1);

    double freq = pow(10000.0, -(double)i / 64.0);
    float ang = (float)((double)s * freq);
    float sn, cs;
    sincosf(ang, &sn, &cs);

    size_t base = (size_t)m * EMB + h * HD + 2 * i;
    float q1 = q[base], q2 = q[base + 1];
    q[base]     = q1 * cs - q2 * sn;
    q[base + 1] = q2 * cs + q1 * sn;
    float k1 = k[base], k2 = k[base + 1];
    k[base]     = k1 * cs - k2 * sn;
    k[base + 1] = k2 * cs + k1 * sn;
}

// ---------------------------------------------------------------------------
// Flash attention (fp32), causal. One block per (q-tile of 64 rows, b*h).
// ---------------------------------------------------------------------------
#define BQ   64
#define BKV  64
#define QP   129
#define VP   132
#define SP   65

__global__ __launch_bounds__(256) void flash_kernel(const float* __restrict__ q,
                                                    const float* __restrict__ k,
                                                    const float* __restrict__ v,
                                                    float* __restrict__ ctx)
{
    extern __shared__ float sm[];
    float* Qs   = sm;
    float* Ks   = Qs + BQ * QP;
    float* Vs   = Ks + BKV * QP;
    float* Ss   = Vs + BKV * VP;
    float* mrow = Ss + BQ * SP;
    float* lrow = mrow + BQ;
    float* srow = lrow + BQ;

    const int qt  = blockIdx.x;
    const int bh  = blockIdx.y;
    const int b   = bh >> 4;
    const int h   = bh & 15;
    const int tid = threadIdx.x;
    const float scale = 0.08838834764831845f;

#pragma unroll
    for (int l = 0; l < 8; l++) {
        int idx = tid + l * 256;
        int r  = idx >> 5;
        int c4 = idx & 31;
        float4 vq = *(const float4*)(q + (size_t)(b * SEQ + qt * BQ + r) * EMB + h * HD + c4 * 4);
        float* dst = &Qs[r * QP + c4 * 4];
        dst[0] = vq.x * scale; dst[1] = vq.y * scale;
        dst[2] = vq.z * scale; dst[3] = vq.w * scale;
    }
    if (tid < BQ) { mrow[tid] = -1e30f; lrow[tid] = 0.f; }

    float acc[4][8];
#pragma unroll
    for (int i = 0; i < 4; i++)
#pragma unroll
        for (int j = 0; j < 8; j++) acc[i][j] = 0.f;

    const int ty = tid >> 4;
    const int tx = tid & 15;
    const int ro = ty * 4;
    const int co = tx * 8;

    for (int kt = 0; kt <= qt; kt++) {
        __syncthreads();
#pragma unroll
        for (int l = 0; l < 8; l++) {
            int idx = tid + l * 256;
            int r  = idx >> 5;
            int c4 = idx & 31;
            size_t goff = (size_t)(b * SEQ + kt * BKV + r) * EMB + h * HD + c4 * 4;
            float4 vk = *(const float4*)(k + goff);
            float* dk = &Ks[r * QP + c4 * 4];
            dk[0] = vk.x; dk[1] = vk.y; dk[2] = vk.z; dk[3] = vk.w;
            float4 vv = *(const float4*)(v + goff);
            *(float4*)&Vs[r * VP + c4 * 4] = vv;
        }
        __syncthreads();

        float s_[4][4];
#pragma unroll
        for (int i = 0; i < 4; i++)
#pragma unroll
            for (int j = 0; j < 4; j++) s_[i][j] = 0.f;
#pragma unroll 4
        for (int d = 0; d < HD; d++) {
            float aq[4], ak[4];
#pragma unroll
            for (int i = 0; i < 4; i++) aq[i] = Qs[(ro + i) * QP + d];
#pragma unroll
            for (int j = 0; j < 4; j++) ak[j] = Ks[(tx * 4 + j) * QP + d];
#pragma unroll
            for (int i = 0; i < 4; i++)
#pragma unroll
                for (int j = 0; j < 4; j++)
                    s_[i][j] = fmaf(aq[i], ak[j], s_[i][j]);
        }
#pragma unroll
        for (int i = 0; i < 4; i++)
#pragma unroll
            for (int j = 0; j < 4; j++) {
                int r = ro + i, c = tx * 4 + j;
                float val = s_[i][j];
                if (kt == qt && c > r) val = -1e30f;
                Ss[r * SP + c] = val;
            }
        __syncthreads();

        {
            int row = tid >> 2, seg = tid & 3;
            float pm = -1e30f;
            for (int c = seg * 16; c < seg * 16 + 16; c++)
                pm = fmaxf(pm, Ss[row * SP + c]);
            pm = fmaxf(pm, __shfl_xor_sync(0xffffffff, pm, 1));
            pm = fmaxf(pm, __shfl_xor_sync(0xffffffff, pm, 2));
            float mold = mrow[row];
            float mnew = fmaxf(mold, pm);
            float psum = 0.f;
            for (int c = seg * 16; c < seg * 16 + 16; c++) {
                float p = __expf(Ss[row * SP + c] - mnew);
                Ss[row * SP + c] = p;
                psum += p;
            }
            psum += __shfl_xor_sync(0xffffffff, psum, 1);
            psum += __shfl_xor_sync(0xffffffff, psum, 2);
            if (seg == 0) {
                float sc = __expf(mold - mnew);
                srow[row] = sc;
                lrow[row] = lrow[row] * sc + psum;
                mrow[row] = mnew;
            }
        }
        __syncthreads();

        float sc[4];
#pragma unroll
        for (int i = 0; i < 4; i++) sc[i] = srow[ro + i];
#pragma unroll
        for (int i = 0; i < 4; i++)
#pragma unroll
            for (int j = 0; j < 8; j++) acc[i][j] *= sc[i];

#pragma unroll 4
        for (int kk = 0; kk < BKV; kk++) {
            float p[4];
#pragma unroll
            for (int i = 0; i < 4; i++) p[i] = Ss[(ro + i) * SP + kk];
            float vv[8];
            *(float4*)(vv)     = *(const float4*)&Vs[kk * VP + co];
            *(float4*)(vv + 4) = *(const float4*)&Vs[kk * VP + co + 4];
#pragma unroll
            for (int i = 0; i < 4; i++)
#pragma unroll
                for (int j = 0; j < 8; j++)
                    acc[i][j] = fmaf(p[i], vv[j], acc[i][j]);
        }
    }

#pragma unroll
    for (int i = 0; i < 4; i++) {
        float inv = 1.0f / lrow[ro + i];
        size_t m = (size_t)(b * SEQ + qt * BQ + ro + i);
        float4 o0 = make_float4(acc[i][0] * inv, acc[i][1] * inv, acc[i][2] * inv, acc[i][3] * inv);
        float4 o1 = make_float4(acc[i][4] * inv, acc[i][5] * inv, acc[i][6] * inv, acc[i][7] * inv);
        *(float4*)(ctx + m * EMB + h * HD + co)     = o0;
        *(float4*)(ctx + m * EMB + h * HD + co + 4) = o1;
    }
}

// ---------------------------------------------------------------------------
// Launch
// ---------------------------------------------------------------------------
extern "C" void kernel_launch(void* const* d_in, const int* in_sizes, int n_in,
                              void* d_out, int out_size)
{
    const float* x  = (const float*)d_in[0];
    const float* Wq = (const float*)d_in[1];
    const float* Wk = (const float*)d_in[2];
    const float* Wv = (const float*)d_in[3];
    const float* Wo = (const float*)d_in[4];
    float* out = (float*)d_out;

    float *pq, *pk, *pv, *pctx;
    cudaGetSymbolAddress((void**)&pq,   g_q);
    cudaGetSymbolAddress((void**)&pk,   g_k);
    cudaGetSymbolAddress((void**)&pv,   g_v);
    cudaGetSymbolAddress((void**)&pctx, g_ctx);

    dim3 gg(EMB / BN, MTOT / BM);     // (16, 64)
    mma_gemm<<<gg, 256>>>(x, Wq, pq, MTOT, EMB);
    mma_gemm<<<gg, 256>>>(x, Wk, pk, MTOT, EMB);
    mma_gemm<<<gg, 256>>>(x, Wv, pv, MTOT, EMB);

    int npairs = MTOT * NH * (HD / 2);
    rope_kernel<<<(npairs + 255) / 256, 256>>>(pq, pk);

    size_t smem = (size_t)(BQ * QP + BKV * QP + BKV * VP + BQ * SP + 3 * BQ) * sizeof(float);
    cudaFuncSetAttribute(flash_kernel, cudaFuncAttributeMaxDynamicSharedMemorySize, (int)smem);
    dim3 gf(SEQ / BQ, BATCH * NH);    // (32, 64)
    flash_kernel<<<gf, 256, smem>>>(pq, pk, pv, pctx);

    mma_gemm<<<gg, 256>>>(pctx, Wo, out, MTOT, EMB);
}

// round 11
// speedup vs baseline: 1.6002x; 1.0662x over previous
#include <cuda_runtime.h>
#include <cuda_bf16.h>
#include <cuda_fp16.h>
#include <math.h>
#include <stdint.h>

#define EMB   2048
#define NH    16
#define HD    128
#define BATCH 4
#define SEQ   2048
#define MTOT  (BATCH*SEQ)   // 8192 rows
#define GK    2048          // GEMM K (fixed)

// Scratch (device globals -- allocation-free per harness rules)
__device__ float g_q[(size_t)MTOT * EMB];
__device__ float g_k[(size_t)MTOT * EMB];
__device__ float g_v[(size_t)MTOT * EMB];
__device__ float g_ctx[(size_t)MTOT * EMB];

// ===========================================================================
// Small PTX helpers (all baseline sm_80+ -- compiles on plain sm_103 target)
// ===========================================================================
__device__ __forceinline__ uint32_t smem_u32(const void* p) {
    uint32_t a;
    asm("{ .reg .u64 t; cvta.to.shared.u64 t, %1; cvt.u32.u64 %0, t; }" : "=r"(a) : "l"(p));
    return a;
}
__device__ __forceinline__ void ldsm4(uint32_t* r, uint32_t addr) {
    asm volatile("ldmatrix.sync.aligned.m8n8.x4.shared.b16 {%0,%1,%2,%3}, [%4];"
        : "=r"(r[0]), "=r"(r[1]), "=r"(r[2]), "=r"(r[3]) : "r"(addr));
}
__device__ __forceinline__ void mma_f16(float* d, const uint32_t* a, uint32_t b0, uint32_t b1) {
    asm volatile("mma.sync.aligned.m16n8k16.row.col.f32.f16.f16.f32 "
        "{%0,%1,%2,%3}, {%4,%5,%6,%7}, {%8,%9}, {%0,%1,%2,%3};"
        : "+f"(d[0]), "+f"(d[1]), "+f"(d[2]), "+f"(d[3])
        : "r"(a[0]), "r"(a[1]), "r"(a[2]), "r"(a[3]), "r"(b0), "r"(b1));
}

// ===========================================================================
// fp16 2-pass HMMA GEMM (NT): C[m][n] = sum_k A[m*K+k] * B[n*K+k], fp32 in/out.
// A split into fp16 hi+lo (exact to ~2^-22); B rounded to fp16 (error 2^-12).
// D = (Ah + Al) * Bh  ->  2 MMA passes, fp32 accum.
// CTA tile 128x128, BK=32, 256 threads = 8 warps (2m x 4n), warp tile 64x32.
// AST = 40 fp16 elems = 80 bytes/row: 16B-aligned for ldmatrix, and
// conflict-free (16B-chunk slot = 5*row mod 8 is a permutation of 8 rows).
// Next K-tile is prefetched into registers during the MMA phase.
// ===========================================================================
#define BM 128
#define BN 128
#define BKK 32
#define AST 40

__global__ __launch_bounds__(256, 1) void mma_gemm(const float* __restrict__ A,
                                                   const float* __restrict__ B,
                                                   float* __restrict__ C,
                                                   int M, int N)
{
    __shared__ __align__(16) __half Ah[BM * AST];
    __shared__ __align__(16) __half Al[BM * AST];
    __shared__ __align__(16) __half Bh[BN * AST];

    const int tid  = threadIdx.x;
    const int lane = tid & 31;
    const int wid  = tid >> 5;
    const int m0 = blockIdx.y * BM;
    const int n0 = blockIdx.x * BN;
    const int wm = (wid & 1) * 64;    // warp m offset within CTA tile
    const int wn = (wid >> 1) * 32;   // warp n offset within CTA tile

    float acc[4][4][4];               // [mt][nt][reg]
#pragma unroll
    for (int i = 0; i < 4; i++)
#pragma unroll
        for (int j = 0; j < 4; j++)
#pragma unroll
            for (int r = 0; r < 4; r++) acc[i][j][r] = 0.f;

    // ldmatrix base addresses (bytes): row = (lane&15), col-half = (lane>>4)*8
    const uint32_t lrow = (lane & 15);
    const uint32_t lcol = (lane >> 4) * 8;   // fp16 elems
    const uint32_t a_base  = smem_u32(Ah) + ((wm + lrow) * AST + lcol) * 2;
    const uint32_t al_base = smem_u32(Al) + ((wm + lrow) * AST + lcol) * 2;
    const uint32_t b_base  = smem_u32(Bh) + ((wn + lrow) * AST + lcol) * 2;

    const int ldrow = tid >> 3;       // 0..31, +32 per unroll step
    const int ldk   = tid & 7;        // float4 slot within 32-col slab
    const float* Aptr = A + (size_t)(m0 + ldrow) * GK + ldk * 4;
    const float* Bptr = B + (size_t)(n0 + ldrow) * GK + ldk * 4;

    // Prologue: prefetch tile 0 into registers
    float4 pa[4], pb[4];
#pragma unroll
    for (int l = 0; l < 4; l++) {
        pa[l] = *(const float4*)(Aptr + (size_t)l * 32 * GK);
        pb[l] = *(const float4*)(Bptr + (size_t)l * 32 * GK);
    }

    for (int k0 = 0; k0 < GK; k0 += BKK) {
        // ---- convert prefetched tile to fp16 hi/lo and store to smem ----
#pragma unroll
        for (int l = 0; l < 4; l++) {
            int row = ldrow + l * 32;
            uint32_t soff = (uint32_t)(row * AST + ldk * 4) * 2;   // bytes

            __half2 h0 = __floats2half2_rn(pa[l].x, pa[l].y);
            __half2 h1 = __floats2half2_rn(pa[l].z, pa[l].w);
            __half2 e0 = __floats2half2_rn(pa[l].x - __low2float(h0),
                                           pa[l].y - __high2float(h0));
            __half2 e1 = __floats2half2_rn(pa[l].z - __low2float(h1),
                                           pa[l].w - __high2float(h1));
            *(__half2*)((char*)Ah + soff)     = h0;
            *(__half2*)((char*)Ah + soff + 4) = h1;
            *(__half2*)((char*)Al + soff)     = e0;
            *(__half2*)((char*)Al + soff + 4) = e1;

            __half2 g0 = __floats2half2_rn(pb[l].x, pb[l].y);
            __half2 g1 = __floats2half2_rn(pb[l].z, pb[l].w);
            *(__half2*)((char*)Bh + soff)     = g0;
            *(__half2*)((char*)Bh + soff + 4) = g1;
        }
        __syncthreads();

        // ---- prefetch next tile (overlaps with MMA below) ----
        if (k0 + BKK < GK) {
#pragma unroll
            for (int l = 0; l < 4; l++) {
                pa[l] = *(const float4*)(Aptr + (size_t)l * 32 * GK + k0 + BKK);
                pb[l] = *(const float4*)(Bptr + (size_t)l * 32 * GK + k0 + BKK);
            }
        }

        // ---- MMA: two k16 steps, 2 passes each ----
#pragma unroll
        for (int ks = 0; ks < 2; ks++) {
            const uint32_t kb = ks * 32;   // 16 fp16 = 32 bytes

            uint32_t afh[4][4], bfh[2][4];
#pragma unroll
            for (int mt = 0; mt < 4; mt++)
                ldsm4(afh[mt], a_base + mt * (16 * AST * 2) + kb);
#pragma unroll
            for (int nh = 0; nh < 2; nh++)
                ldsm4(bfh[nh], b_base + nh * (16 * AST * 2) + kb);

            // hi * B
#pragma unroll
            for (int mt = 0; mt < 4; mt++)
#pragma unroll
                for (int nt = 0; nt < 4; nt++)
                    mma_f16(acc[mt][nt], afh[mt], bfh[nt >> 1][nt & 1], bfh[nt >> 1][(nt & 1) + 2]);

            // lo * B
            uint32_t afl[4][4];
#pragma unroll
            for (int mt = 0; mt < 4; mt++)
                ldsm4(afl[mt], al_base + mt * (16 * AST * 2) + kb);
#pragma unroll
            for (int mt = 0; mt < 4; mt++)
#pragma unroll
                for (int nt = 0; nt < 4; nt++)
                    mma_f16(acc[mt][nt], afl[mt], bfh[nt >> 1][nt & 1], bfh[nt >> 1][(nt & 1) + 2]);
        }
        __syncthreads();
    }

    // ---- epilogue: direct float2 stores ----
    const int erow = lane >> 2;
    const int ecol = (lane & 3) * 2;
#pragma unroll
    for (int mt = 0; mt < 4; mt++) {
#pragma unroll
        for (int nt = 0; nt < 4; nt++) {
            int row = m0 + wm + mt * 16 + erow;
            int col = n0 + wn + nt * 8 + ecol;
            *(float2*)(C + (size_t)row * N + col) =
                make_float2(acc[mt][nt][0], acc[mt][nt][1]);
            *(float2*)(C + (size_t)(row + 8) * N + col) =
                make_float2(acc[mt][nt][2], acc[mt][nt][3]);
        }
    }
}

// ---------------------------------------------------------------------------
// RoPE (interleaved pairs), applied in-place to q and k.
// ---------------------------------------------------------------------------
__global__ void rope_kernel(float* __restrict__ q, float* __restrict__ k)
{
    int idx = blockIdx.x * blockDim.x + threadIdx.x;
    if (idx >= MTOT * NH * (HD / 2)) return;
    int i = idx & 63;
    int h = (idx >> 6) & 15;
    int m = idx >> 10;
    int s = m & (SEQ - 1);

    double freq = pow(10000.0, -(double)i / 64.0);
    float ang = (float)((double)s * freq);
    float sn, cs;
    sincosf(ang, &sn, &cs);

    size_t base = (size_t)m * EMB + h * HD + 2 * i;
    float q1 = q[base], q2 = q[base + 1];
    q[base]     = q1 * cs - q2 * sn;
    q[base + 1] = q2 * cs + q1 * sn;
    float k1 = k[base], k2 = k[base + 1];
    k[base]     = k1 * cs - k2 * sn;
    k[base + 1] = k2 * cs + k1 * sn;
}

// ---------------------------------------------------------------------------
// Flash attention (fp32), causal. One block per (q-tile of 64 rows, b*h).
// ---------------------------------------------------------------------------
#define BQ   64
#define BKV  64
#define QP   129
#define VP   132
#define SP   65

__global__ __launch_bounds__(256) void flash_kernel(const float* __restrict__ q,
                                                    const float* __restrict__ k,
                                                    const float* __restrict__ v,
                                                    float* __restrict__ ctx)
{
    extern __shared__ float sm[];
    float* Qs   = sm;
    float* Ks   = Qs + BQ * QP;
    float* Vs   = Ks + BKV * QP;
    float* Ss   = Vs + BKV * VP;
    float* mrow = Ss + BQ * SP;
    float* lrow = mrow + BQ;
    float* srow = lrow + BQ;

    const int qt  = blockIdx.x;
    const int bh  = blockIdx.y;
    const int b   = bh >> 4;
    const int h   = bh & 15;
    const int tid = threadIdx.x;
    const float scale = 0.08838834764831845f;

#pragma unroll
    for (int l = 0; l < 8; l++) {
        int idx = tid + l * 256;
        int r  = idx >> 5;
        int c4 = idx & 31;
        float4 vq = *(const float4*)(q + (size_t)(b * SEQ + qt * BQ + r) * EMB + h * HD + c4 * 4);
        float* dst = &Qs[r * QP + c4 * 4];
        dst[0] = vq.x * scale; dst[1] = vq.y * scale;
        dst[2] = vq.z * scale; dst[3] = vq.w * scale;
    }
    if (tid < BQ) { mrow[tid] = -1e30f; lrow[tid] = 0.f; }

    float acc[4][8];
#pragma unroll
    for (int i = 0; i < 4; i++)
#pragma unroll
        for (int j = 0; j < 8; j++) acc[i][j] = 0.f;

    const int ty = tid >> 4;
    const int tx = tid & 15;
    const int ro = ty * 4;
    const int co = tx * 8;

    for (int kt = 0; kt <= qt; kt++) {
        __syncthreads();
#pragma unroll
        for (int l = 0; l < 8; l++) {
            int idx = tid + l * 256;
            int r  = idx >> 5;
            int c4 = idx & 31;
            size_t goff = (size_t)(b * SEQ + kt * BKV + r) * EMB + h * HD + c4 * 4;
            float4 vk = *(const float4*)(k + goff);
            float* dk = &Ks[r * QP + c4 * 4];
            dk[0] = vk.x; dk[1] = vk.y; dk[2] = vk.z; dk[3] = vk.w;
            float4 vv = *(const float4*)(v + goff);
            *(float4*)&Vs[r * VP + c4 * 4] = vv;
        }
        __syncthreads();

        float s_[4][4];
#pragma unroll
        for (int i = 0; i < 4; i++)
#pragma unroll
            for (int j = 0; j < 4; j++) s_[i][j] = 0.f;
#pragma unroll 4
        for (int d = 0; d < HD; d++) {
            float aq[4], ak[4];
#pragma unroll
            for (int i = 0; i < 4; i++) aq[i] = Qs[(ro + i) * QP + d];
#pragma unroll
            for (int j = 0; j < 4; j++) ak[j] = Ks[(tx * 4 + j) * QP + d];
#pragma unroll
            for (int i = 0; i < 4; i++)
#pragma unroll
                for (int j = 0; j < 4; j++)
                    s_[i][j] = fmaf(aq[i], ak[j], s_[i][j]);
        }
#pragma unroll
        for (int i = 0; i < 4; i++)
#pragma unroll
            for (int j = 0; j < 4; j++) {
                int r = ro + i, c = tx * 4 + j;
                float val = s_[i][j];
                if (kt == qt && c > r) val = -1e30f;
                Ss[r * SP + c] = val;
            }
        __syncthreads();

        {
            int row = tid >> 2, seg = tid & 3;
            float pm = -1e30f;
            for (int c = seg * 16; c < seg * 16 + 16; c++)
                pm = fmaxf(pm, Ss[row * SP + c]);
            pm = fmaxf(pm, __shfl_xor_sync(0xffffffff, pm, 1));
            pm = fmaxf(pm, __shfl_xor_sync(0xffffffff, pm, 2));
            float mold = mrow[row];
            float mnew = fmaxf(mold, pm);
            float psum = 0.f;
            for (int c = seg * 16; c < seg * 16 + 16; c++) {
                float p = __expf(Ss[row * SP + c] - mnew);
                Ss[row * SP + c] = p;
                psum += p;
            }
            psum += __shfl_xor_sync(0xffffffff, psum, 1);
            psum += __shfl_xor_sync(0xffffffff, psum, 2);
            if (seg == 0) {
                float sc = __expf(mold - mnew);
                srow[row] = sc;
                lrow[row] = lrow[row] * sc + psum;
                mrow[row] = mnew;
            }
        }
        __syncthreads();

        float sc[4];
#pragma unroll
        for (int i = 0; i < 4; i++) sc[i] = srow[ro + i];
#pragma unroll
        for (int i = 0; i < 4; i++)
#pragma unroll
            for (int j = 0; j < 8; j++) acc[i][j] *= sc[i];

#pragma unroll 4
        for (int kk = 0; kk < BKV; kk++) {
            float p[4];
#pragma unroll
            for (int i = 0; i < 4; i++) p[i] = Ss[(ro + i) * SP + kk];
            float vv[8];
            *(float4*)(vv)     = *(const float4*)&Vs[kk * VP + co];
            *(float4*)(vv + 4) = *(const float4*)&Vs[kk * VP + co + 4];
#pragma unroll
            for (int i = 0; i < 4; i++)
#pragma unroll
                for (int j = 0; j < 8; j++)
                    acc[i][j] = fmaf(p[i], vv[j], acc[i][j]);
        }
    }

#pragma unroll
    for (int i = 0; i < 4; i++) {
        float inv = 1.0f / lrow[ro + i];
        size_t m = (size_t)(b * SEQ + qt * BQ + ro + i);
        float4 o0 = make_float4(acc[i][0] * inv, acc[i][1] * inv, acc[i][2] * inv, acc[i][3] * inv);
        float4 o1 = make_float4(acc[i][4] * inv, acc[i][5] * inv, acc[i][6] * inv, acc[i][7] * inv);
        *(float4*)(ctx + m * EMB + h * HD + co)     = o0;
        *(float4*)(ctx + m * EMB + h * HD + co + 4) = o1;
    }
}

// ---------------------------------------------------------------------------
// Launch
// ---------------------------------------------------------------------------
extern "C" void kernel_launch(void* const* d_in, const int* in_sizes, int n_in,
                              void* d_out, int out_size)
{
    const float* x  = (const float*)d_in[0];
    const float* Wq = (const float*)d_in[1];
    const float* Wk = (const float*)d_in[2];
    const float* Wv = (const float*)d_in[3];
    const float* Wo = (const float*)d_in[4];
    float* out = (float*)d_out;

    float *pq, *pk, *pv, *pctx;
    cudaGetSymbolAddress((void**)&pq,   g_q);
    cudaGetSymbolAddress((void**)&pk,   g_k);
    cudaGetSymbolAddress((void**)&pv,   g_v);
    cudaGetSymbolAddress((void**)&pctx, g_ctx);

    dim3 gg(EMB / BN, MTOT / BM);     // (16, 64)
    mma_gemm<<<gg, 256>>>(x, Wq, pq, MTOT, EMB);
    mma_gemm<<<gg, 256>>>(x, Wk, pk, MTOT, EMB);
    mma_gemm<<<gg, 256>>>(x, Wv, pv, MTOT, EMB);

    int npairs = MTOT * NH * (HD / 2);
    rope_kernel<<<(npairs + 255) / 256, 256>>>(pq, pk);

    size_t smem = (size_t)(BQ * QP + BKV * QP + BKV * VP + BQ * SP + 3 * BQ) * sizeof(float);
    cudaFuncSetAttribute(flash_kernel, cudaFuncAttributeMaxDynamicSharedMemorySize, (int)smem);
    dim3 gf(SEQ / BQ, BATCH * NH);    // (32, 64)
    flash_kernel<<<gf, 256, smem>>>(pq, pk, pv, pctx);

    mma_gemm<<<gg, 256>>>(pctx, Wo, out, MTOT, EMB);
}

// round 13
// speedup vs baseline: 1.6904x; 1.0564x over previous
#include <cuda_runtime.h>
#include <cuda_fp16.h>
#include <math.h>
#include <stdint.h>

#define EMB   2048
#define NH    16
#define HD    128
#define BATCH 4
#define SEQ   2048
#define MTOT  (BATCH*SEQ)   // 8192 rows
#define GK    2048          // GEMM K (fixed)

// Scratch (device globals -- allocation-free per harness rules)
__device__ float g_q[(size_t)MTOT * EMB];
__device__ float g_k[(size_t)MTOT * EMB];
__device__ float g_v[(size_t)MTOT * EMB];
__device__ float g_ctx[(size_t)MTOT * EMB];
// fp16 staging
__device__ __half g_xh[(size_t)MTOT * EMB];
__device__ __half g_xl[(size_t)MTOT * EMB];
__device__ __half g_ch[(size_t)MTOT * EMB];
__device__ __half g_cl[(size_t)MTOT * EMB];
__device__ __half g_wqh[(size_t)EMB * EMB];
__device__ __half g_wkh[(size_t)EMB * EMB];
__device__ __half g_wvh[(size_t)EMB * EMB];
__device__ __half g_woh[(size_t)EMB * EMB];

// ===========================================================================
// PTX helpers (baseline sm_80+)
// ===========================================================================
__device__ __forceinline__ uint32_t smem_u32(const void* p) {
    uint32_t a;
    asm("{ .reg .u64 t; cvta.to.shared.u64 t, %1; cvt.u32.u64 %0, t; }" : "=r"(a) : "l"(p));
    return a;
}
__device__ __forceinline__ void ldsm4(uint32_t* r, uint32_t addr) {
    asm volatile("ldmatrix.sync.aligned.m8n8.x4.shared.b16 {%0,%1,%2,%3}, [%4];"
        : "=r"(r[0]), "=r"(r[1]), "=r"(r[2]), "=r"(r[3]) : "r"(addr));
}
__device__ __forceinline__ void mma_f16(float* d, const uint32_t* a, uint32_t b0, uint32_t b1) {
    asm volatile("mma.sync.aligned.m16n8k16.row.col.f32.f16.f16.f32 "
        "{%0,%1,%2,%3}, {%4,%5,%6,%7}, {%8,%9}, {%0,%1,%2,%3};"
        : "+f"(d[0]), "+f"(d[1]), "+f"(d[2]), "+f"(d[3])
        : "r"(a[0]), "r"(a[1]), "r"(a[2]), "r"(a[3]), "r"(b0), "r"(b1));
}
__device__ __forceinline__ void cp16(uint32_t dst, const void* src) {
    asm volatile("cp.async.cg.shared.global [%0], [%1], 16;" :: "r"(dst), "l"(src));
}
#define CP_COMMIT() asm volatile("cp.async.commit_group;" ::: "memory")
#define CP_WAIT(n)  asm volatile("cp.async.wait_group %0;" :: "n"(n) : "memory")

// ===========================================================================
// Conversion kernels (hoisted out of the GEMM hot loop)
// ===========================================================================
__global__ void cvt_hilo(const float* __restrict__ in, __half* __restrict__ hi,
                         __half* __restrict__ lo, int n4)
{
    int i = blockIdx.x * blockDim.x + threadIdx.x;
    if (i >= n4) return;
    float4 v = *(const float4*)(in + (size_t)i * 4);
    __half2 h0 = __floats2half2_rn(v.x, v.y);
    __half2 h1 = __floats2half2_rn(v.z, v.w);
    __half2 e0 = __floats2half2_rn(v.x - __low2float(h0), v.y - __high2float(h0));
    __half2 e1 = __floats2half2_rn(v.z - __low2float(h1), v.w - __high2float(h1));
    *(__half2*)(hi + (size_t)i * 4)     = h0;
    *(__half2*)(hi + (size_t)i * 4 + 2) = h1;
    *(__half2*)(lo + (size_t)i * 4)     = e0;
    *(__half2*)(lo + (size_t)i * 4 + 2) = e1;
}
__global__ void cvt_hi(const float* __restrict__ in, __half* __restrict__ hi, int n4)
{
    int i = blockIdx.x * blockDim.x + threadIdx.x;
    if (i >= n4) return;
    float4 v = *(const float4*)(in + (size_t)i * 4);
    *(__half2*)(hi + (size_t)i * 4)     = __floats2half2_rn(v.x, v.y);
    *(__half2*)(hi + (size_t)i * 4 + 2) = __floats2half2_rn(v.z, v.w);
}

// ===========================================================================
// fp16 2-pass HMMA GEMM (NT), cp.async double-buffered.
// C[m][n] = sum_k (Ah+Al)[m][k] * Bh[n][k], fp32 accum.
// CTA tile 128x128, BK=32, 256 threads = 8 warps (2m x 4n), warp tile 64x32.
// AST = 40 fp16 (80B/row): 16B-aligned rows, conflict-free ldmatrix phases.
// ===========================================================================
#define BM 128
#define BN 128
#define BKK 32
#define AST 40
#define NIT (GK / BKK)                 // 64
#define TILEB (BM * AST * 2)           // 10240 bytes per tile array
#define BUFB  (3 * TILEB)              // 30720 bytes per buffer
#define SMEM_GEMM (2 * BUFB)           // 61440

__global__ __launch_bounds__(256) void mma_gemm(const __half* __restrict__ Ah,
                                                const __half* __restrict__ Al,
                                                const __half* __restrict__ Bh,
                                                float* __restrict__ C,
                                                int M, int N)
{
    extern __shared__ char smem[];
    const uint32_t sb = smem_u32(smem);

    const int tid  = threadIdx.x;
    const int lane = tid & 31;
    const int wid  = tid >> 5;
    const int m0 = blockIdx.y * BM;
    const int n0 = blockIdx.x * BN;
    const int wm = (wid & 1) * 64;
    const int wn = (wid >> 1) * 32;

    float acc[4][4][4];
#pragma unroll
    for (int i = 0; i < 4; i++)
#pragma unroll
        for (int j = 0; j < 4; j++)
#pragma unroll
            for (int r = 0; r < 4; r++) acc[i][j][r] = 0.f;

    // cp.async tile loader: 128 rows x 32 halfs = 512 x 16B chunks per array;
    // 256 threads -> 2 chunks each. row = idx>>2, chunk = idx&3.
    const int r0 = tid >> 2;           // rows 0..63 (l=0), +64 (l=1)
    const int c0 = tid & 3;            // 16B chunk within row
    const __half* Ap = Ah + (size_t)(m0 + r0) * GK + c0 * 8;
    const __half* Lp = Al + (size_t)(m0 + r0) * GK + c0 * 8;
    const __half* Bp = Bh + (size_t)(n0 + r0) * GK + c0 * 8;
    const uint32_t sA = sb + r0 * 80 + c0 * 16;

#define ISSUE(it, buf) do {                                                   \
        int kofs = (it) * BKK;                                                \
        uint32_t bb = (buf) * BUFB;                                           \
        cp16(sA + bb,                      Ap + kofs);                        \
        cp16(sA + bb + (64*80),            Ap + kofs + (size_t)64 * GK);      \
        cp16(sA + bb + TILEB,              Lp + kofs);                        \
        cp16(sA + bb + TILEB + (64*80),    Lp + kofs + (size_t)64 * GK);      \
        cp16(sA + bb + 2*TILEB,            Bp + kofs);                        \
        cp16(sA + bb + 2*TILEB + (64*80),  Bp + kofs + (size_t)64 * GK);      \
        CP_COMMIT();                                                          \
    } while (0)

    // ldmatrix base offsets (within a buffer)
    const uint32_t lrow = (lane & 15);
    const uint32_t lcol = (lane >> 4) * 8;
    const uint32_t aoff  = ((wm + lrow) * AST + lcol) * 2;
    const uint32_t boff  = ((wn + lrow) * AST + lcol) * 2 + 2 * TILEB;

    ISSUE(0, 0);

    for (int it = 0; it < NIT; it++) {
        const int buf = it & 1;
        if (it + 1 < NIT) {
            ISSUE(it + 1, buf ^ 1);
            CP_WAIT(1);
        } else {
            CP_WAIT(0);
        }
        __syncthreads();

        const uint32_t a_base  = sb + buf * BUFB + aoff;
        const uint32_t al_base = a_base + TILEB;
        const uint32_t b_base  = sb + buf * BUFB + boff;

#pragma unroll
        for (int ks = 0; ks < 2; ks++) {
            const uint32_t kb = ks * 32;

            uint32_t afh[4][4], bfh[2][4];
#pragma unroll
            for (int mt = 0; mt < 4; mt++)
                ldsm4(afh[mt], a_base + mt * (16 * AST * 2) + kb);
#pragma unroll
            for (int nh = 0; nh < 2; nh++)
                ldsm4(bfh[nh], b_base + nh * (16 * AST * 2) + kb);

#pragma unroll
            for (int mt = 0; mt < 4; mt++)
#pragma unroll
                for (int nt = 0; nt < 4; nt++)
                    mma_f16(acc[mt][nt], afh[mt], bfh[nt >> 1][nt & 1], bfh[nt >> 1][(nt & 1) + 2]);

            uint32_t afl[4][4];
#pragma unroll
            for (int mt = 0; mt < 4; mt++)
                ldsm4(afl[mt], al_base + mt * (16 * AST * 2) + kb);
#pragma unroll
            for (int mt = 0; mt < 4; mt++)
#pragma unroll
                for (int nt = 0; nt < 4; nt++)
                    mma_f16(acc[mt][nt], afl[mt], bfh[nt >> 1][nt & 1], bfh[nt >> 1][(nt & 1) + 2]);
        }
        __syncthreads();
    }

    const int erow = lane >> 2;
    const int ecol = (lane & 3) * 2;
#pragma unroll
    for (int mt = 0; mt < 4; mt++) {
#pragma unroll
        for (int nt = 0; nt < 4; nt++) {
            int row = m0 + wm + mt * 16 + erow;
            int col = n0 + wn + nt * 8 + ecol;
            *(float2*)(C + (size_t)row * N + col) =
                make_float2(acc[mt][nt][0], acc[mt][nt][1]);
            *(float2*)(C + (size_t)(row + 8) * N + col) =
                make_float2(acc[mt][nt][2], acc[mt][nt][3]);
        }
    }
#undef ISSUE
}

// ---------------------------------------------------------------------------
// RoPE (interleaved pairs), in-place on q and k.
// ---------------------------------------------------------------------------
__global__ void rope_kernel(float* __restrict__ q, float* __restrict__ k)
{
    int idx = blockIdx.x * blockDim.x + threadIdx.x;
    if (idx >= MTOT * NH * (HD / 2)) return;
    int i = idx & 63;
    int h = (idx >> 6) & 15;
    int m = idx >> 10;
    int s = m & (SEQ - 1);

    double freq = pow(10000.0, -(double)i / 64.0);
    float ang = (float)((double)s * freq);
    float sn, cs;
    sincosf(ang, &sn, &cs);

    size_t base = (size_t)m * EMB + h * HD + 2 * i;
    float q1 = q[base], q2 = q[base + 1];
    q[base]     = q1 * cs - q2 * sn;
    q[base + 1] = q2 * cs + q1 * sn;
    float k1 = k[base], k2 = k[base + 1];
    k[base]     = k1 * cs - k2 * sn;
    k[base + 1] = k2 * cs + k1 * sn;
}

// ---------------------------------------------------------------------------
// Flash attention (fp32), causal. One block per (q-tile of 64 rows, b*h).
// ---------------------------------------------------------------------------
#define BQ   64
#define BKV  64
#define QP   129
#define VP   132
#define SP   65

__global__ __launch_bounds__(256) void flash_kernel(const float* __restrict__ q,
                                                    const float* __restrict__ k,
                                                    const float* __restrict__ v,
                                                    float* __restrict__ ctx)
{
    extern __shared__ float sm[];
    float* Qs   = sm;
    float* Ks   = Qs + BQ * QP;
    float* Vs   = Ks + BKV * QP;
    float* Ss   = Vs + BKV * VP;
    float* mrow = Ss + BQ * SP;
    float* lrow = mrow + BQ;
    float* srow = lrow + BQ;

    const int qt  = blockIdx.x;
    const int bh  = blockIdx.y;
    const int b   = bh >> 4;
    const int h   = bh & 15;
    const int tid = threadIdx.x;
    const float scale = 0.08838834764831845f;

#pragma unroll
    for (int l = 0; l < 8; l++) {
        int idx = tid + l * 256;
        int r  = idx >> 5;
        int c4 = idx & 31;
        float4 vq = *(const float4*)(q + (size_t)(b * SEQ + qt * BQ + r) * EMB + h * HD + c4 * 4);
        float* dst = &Qs[r * QP + c4 * 4];
        dst[0] = vq.x * scale; dst[1] = vq.y * scale;
        dst[2] = vq.z * scale; dst[3] = vq.w * scale;
    }
    if (tid < BQ) { mrow[tid] = -1e30f; lrow[tid] = 0.f; }

    float acc[4][8];
#pragma unroll
    for (int i = 0; i < 4; i++)
#pragma unroll
        for (int j = 0; j < 8; j++) acc[i][j] = 0.f;

    const int ty = tid >> 4;
    const int tx = tid & 15;
    const int ro = ty * 4;
    const int co = tx * 8;

    for (int kt = 0; kt <= qt; kt++) {
        __syncthreads();
#pragma unroll
        for (int l = 0; l < 8; l++) {
            int idx = tid + l * 256;
            int r  = idx >> 5;
            int c4 = idx & 31;
            size_t goff = (size_t)(b * SEQ + kt * BKV + r) * EMB + h * HD + c4 * 4;
            float4 vk = *(const float4*)(k + goff);
            float* dk = &Ks[r * QP + c4 * 4];
            dk[0] = vk.x; dk[1] = vk.y; dk[2] = vk.z; dk[3] = vk.w;
            float4 vv = *(const float4*)(v + goff);
            *(float4*)&Vs[r * VP + c4 * 4] = vv;
        }
        __syncthreads();

        float s_[4][4];
#pragma unroll
        for (int i = 0; i < 4; i++)
#pragma unroll
            for (int j = 0; j < 4; j++) s_[i][j] = 0.f;
#pragma unroll 4
        for (int d = 0; d < HD; d++) {
            float aq[4], ak[4];
#pragma unroll
            for (int i = 0; i < 4; i++) aq[i] = Qs[(ro + i) * QP + d];
#pragma unroll
            for (int j = 0; j < 4; j++) ak[j] = Ks[(tx * 4 + j) * QP + d];
#pragma unroll
            for (int i = 0; i < 4; i++)
#pragma unroll
                for (int j = 0; j < 4; j++)
                    s_[i][j] = fmaf(aq[i], ak[j], s_[i][j]);
        }
#pragma unroll
        for (int i = 0; i < 4; i++)
#pragma unroll
            for (int j = 0; j < 4; j++) {
                int r = ro + i, c = tx * 4 + j;
                float val = s_[i][j];
                if (kt == qt && c > r) val = -1e30f;
                Ss[r * SP + c] = val;
            }
        __syncthreads();

        {
            int row = tid >> 2, seg = tid & 3;
            float pm = -1e30f;
            for (int c = seg * 16; c < seg * 16 + 16; c++)
                pm = fmaxf(pm, Ss[row * SP + c]);
            pm = fmaxf(pm, __shfl_xor_sync(0xffffffff, pm, 1));
            pm = fmaxf(pm, __shfl_xor_sync(0xffffffff, pm, 2));
            float mold = mrow[row];
            float mnew = fmaxf(mold, pm);
            float psum = 0.f;
            for (int c = seg * 16; c < seg * 16 + 16; c++) {
                float p = __expf(Ss[row * SP + c] - mnew);
                Ss[row * SP + c] = p;
                psum += p;
            }
            psum += __shfl_xor_sync(0xffffffff, psum, 1);
            psum += __shfl_xor_sync(0xffffffff, psum, 2);
            if (seg == 0) {
                float sc = __expf(mold - mnew);
                srow[row] = sc;
                lrow[row] = lrow[row] * sc + psum;
                mrow[row] = mnew;
            }
        }
        __syncthreads();

        float sc[4];
#pragma unroll
        for (int i = 0; i < 4; i++) sc[i] = srow[ro + i];
#pragma unroll
        for (int i = 0; i < 4; i++)
#pragma unroll
            for (int j = 0; j < 8; j++) acc[i][j] *= sc[i];

#pragma unroll 4
        for (int kk = 0; kk < BKV; kk++) {
            float p[4];
#pragma unroll
            for (int i = 0; i < 4; i++) p[i] = Ss[(ro + i) * SP + kk];
            float vv[8];
            *(float4*)(vv)     = *(const float4*)&Vs[kk * VP + co];
            *(float4*)(vv + 4) = *(const float4*)&Vs[kk * VP + co + 4];
#pragma unroll
            for (int i = 0; i < 4; i++)
#pragma unroll
                for (int j = 0; j < 8; j++)
                    acc[i][j] = fmaf(p[i], vv[j], acc[i][j]);
        }
    }

#pragma unroll
    for (int i = 0; i < 4; i++) {
        float inv = 1.0f / lrow[ro + i];
        size_t m = (size_t)(b * SEQ + qt * BQ + ro + i);
        float4 o0 = make_float4(acc[i][0] * inv, acc[i][1] * inv, acc[i][2] * inv, acc[i][3] * inv);
        float4 o1 = make_float4(acc[i][4] * inv, acc[i][5] * inv, acc[i][6] * inv, acc[i][7] * inv);
        *(float4*)(ctx + m * EMB + h * HD + co)     = o0;
        *(float4*)(ctx + m * EMB + h * HD + co + 4) = o1;
    }
}

// ---------------------------------------------------------------------------
// Launch
// ---------------------------------------------------------------------------
extern "C" void kernel_launch(void* const* d_in, const int* in_sizes, int n_in,
                              void* d_out, int out_size)
{
    const float* x  = (const float*)d_in[0];
    const float* Wq = (const float*)d_in[1];
    const float* Wk = (const float*)d_in[2];
    const float* Wv = (const float*)d_in[3];
    const float* Wo = (const float*)d_in[4];
    float* out = (float*)d_out;

    float *pq, *pk, *pv, *pctx;
    __half *pxh, *pxl, *pch, *pcl, *pwqh, *pwkh, *pwvh, *pwoh;
    cudaGetSymbolAddress((void**)&pq,   g_q);
    cudaGetSymbolAddress((void**)&pk,   g_k);
    cudaGetSymbolAddress((void**)&pv,   g_v);
    cudaGetSymbolAddress((void**)&pctx, g_ctx);
    cudaGetSymbolAddress((void**)&pxh,  g_xh);
    cudaGetSymbolAddress((void**)&pxl,  g_xl);
    cudaGetSymbolAddress((void**)&pch,  g_ch);
    cudaGetSymbolAddress((void**)&pcl,  g_cl);
    cudaGetSymbolAddress((void**)&pwqh, g_wqh);
    cudaGetSymbolAddress((void**)&pwkh, g_wkh);
    cudaGetSymbolAddress((void**)&pwvh, g_wvh);
    cudaGetSymbolAddress((void**)&pwoh, g_woh);

    cudaFuncSetAttribute(mma_gemm, cudaFuncAttributeMaxDynamicSharedMemorySize, SMEM_GEMM);

    // fp16 staging conversions
    int nx4 = (MTOT * EMB) / 4, nw4 = (EMB * EMB) / 4;
    cvt_hilo<<<(nx4 + 255) / 256, 256>>>(x, pxh, pxl, nx4);
    cvt_hi<<<(nw4 + 255) / 256, 256>>>(Wq, pwqh, nw4);
    cvt_hi<<<(nw4 + 255) / 256, 256>>>(Wk, pwkh, nw4);
    cvt_hi<<<(nw4 + 255) / 256, 256>>>(Wv, pwvh, nw4);
    cvt_hi<<<(nw4 + 255) / 256, 256>>>(Wo, pwoh, nw4);

    dim3 gg(EMB / BN, MTOT / BM);     // (16, 64)
    mma_gemm<<<gg, 256, SMEM_GEMM>>>(pxh, pxl, pwqh, pq, MTOT, EMB);
    mma_gemm<<<gg, 256, SMEM_GEMM>>>(pxh, pxl, pwkh, pk, MTOT, EMB);
    mma_gemm<<<gg, 256, SMEM_GEMM>>>(pxh, pxl, pwvh, pv, MTOT, EMB);

    int npairs = MTOT * NH * (HD / 2);
    rope_kernel<<<(npairs + 255) / 256, 256>>>(pq, pk);

    size_t smem = (size_t)(BQ * QP + BKV * QP + BKV * VP + BQ * SP + 3 * BQ) * sizeof(float);
    cudaFuncSetAttribute(flash_kernel, cudaFuncAttributeMaxDynamicSharedMemorySize, (int)smem);
    dim3 gf(SEQ / BQ, BATCH * NH);    // (32, 64)
    flash_kernel<<<gf, 256, smem>>>(pq, pk, pv, pctx);

    cvt_hilo<<<(nx4 + 255) / 256, 256>>>(pctx, pch, pcl, nx4);
    mma_gemm<<<gg, 256, SMEM_GEMM>>>(pch, pcl, pwoh, out, MTOT, EMB);
}